// round 2
// baseline (speedup 1.0000x reference)
#include <cuda_runtime.h>
#include <math.h>

#define N_NODES 8192
#define F_DIM   64
#define H_DIM   128
#define R_DIM   3
#define DEG     32
#define K_TOP   32
#define E_EDGES (N_NODES*DEG)
#define TEMP    0.3f
#define NEG     0.2f
#define EPS_LN  1e-5f
#define THRESH  1e-6f

#define A1_BLOCKS 256   // 32 nodes per block

// deterministic scratch (no atomics)
__device__ float g_part_gs[A1_BLOCKS * F_DIM];
__device__ float g_part_cont[A1_BLOCKS];
__device__ float g_regime[R_DIM];
__device__ float g_amp;
__device__ int   g_is64;

// ---------------------------------------------------------------------------
// detect int32 vs int64 edge_index. src = repeat(arange(N), 32):
//  int64 layout: ((ll*)p)[32] == src[32] == 1
//  int32 layout: ((ll*)p)[32] == (src[64]=2, src[65]=2) == 0x0000000200000002
__global__ void kDetect(const void* eidx) {
    const long long* p = (const long long*)eidx;
    g_is64 = (p[32] == 1LL) ? 1 : 0;
}

// ---------------------------------------------------------------------------
// A1: per-block (32 nodes) partial column sums of x, and partial contagion sums
__global__ void kA1(const float* __restrict__ x,
                    const float* __restrict__ Wc1, const float* __restrict__ bc1,
                    const float* __restrict__ Wc2, const float* __restrict__ bc2) {
    __shared__ float xs[32][64];
    __shared__ float colsum[4][64];
    __shared__ float cwarp[8];
    int t = threadIdx.x, b = blockIdx.x;
    int base = b * 32;
    for (int idx = t; idx < 32 * 64; idx += 256)
        xs[idx >> 6][idx & 63] = x[base * 64 + idx];
    __syncthreads();
    // gs partials
    {
        int col = t & 63, g = t >> 6;
        float s = 0.f;
        #pragma unroll
        for (int rr = 0; rr < 8; rr++) s += xs[g * 8 + rr][col];
        colsum[g][col] = s;
    }
    // contagion: warp w -> local nodes w*4 .. w*4+3
    int w = t >> 5, l = t & 31;
    float csum = 0.f;
    for (int q = 0; q < 4; q++) {
        int node = w * 4 + q;
        float a0 = bc1[l], a1 = bc1[l + 32], a2 = bc1[l + 64], a3 = bc1[l + 96];
        for (int d = 0; d < 64; d++) {
            float xv = xs[node][d];
            const float* Wd = Wc1 + d * 128;
            a0 += xv * Wd[l];      a1 += xv * Wd[l + 32];
            a2 += xv * Wd[l + 64]; a3 += xv * Wd[l + 96];
        }
        float s = fmaxf(a0, 0.f) * Wc2[l]      + fmaxf(a1, 0.f) * Wc2[l + 32]
                + fmaxf(a2, 0.f) * Wc2[l + 64] + fmaxf(a3, 0.f) * Wc2[l + 96];
        #pragma unroll
        for (int off = 16; off; off >>= 1) s += __shfl_xor_sync(0xffffffffu, s, off);
        if (l == 0) csum += 1.f / (1.f + expf(-(s + bc2[0])));
    }
    if (l == 0) cwarp[w] = csum;
    __syncthreads();
    if (t < 64) g_part_gs[b * 64 + t] = colsum[0][t] + colsum[1][t] + colsum[2][t] + colsum[3][t];
    if (t == 0) {
        float s = 0.f;
        for (int i = 0; i < 8; i++) s += cwarp[i];
        g_part_cont[b] = s;
    }
}

// ---------------------------------------------------------------------------
// A2: finalize gs mean, regime probs, contagion amp (1 block, 128 threads)
__global__ void kA2(const float* __restrict__ Wr1, const float* __restrict__ br1,
                    const float* __restrict__ Wr2, const float* __restrict__ br2) {
    __shared__ float gs[64];
    __shared__ float hr[128];
    int t = threadIdx.x;
    if (t < 64) {
        float s = 0.f;
        for (int b = 0; b < A1_BLOCKS; b++) s += g_part_gs[b * 64 + t];
        gs[t] = s / (float)N_NODES;
    }
    __syncthreads();
    {
        float a = br1[t];
        for (int d = 0; d < 64; d++) a += gs[d] * Wr1[d * 128 + t];
        hr[t] = fmaxf(a, 0.f);
    }
    __syncthreads();
    if (t == 0) {
        float lg[3];
        for (int r = 0; r < 3; r++) {
            float a = br2[r];
            for (int h = 0; h < 128; h++) a += hr[h] * Wr2[h * 3 + r];
            lg[r] = a;
        }
        float m = fmaxf(lg[0], fmaxf(lg[1], lg[2]));
        float e0 = expf(lg[0] - m), e1 = expf(lg[1] - m), e2 = expf(lg[2] - m);
        float s = e0 + e1 + e2;
        g_regime[0] = e0 / s; g_regime[1] = e1 / s; g_regime[2] = e2 / s;
        float c = 0.f;
        for (int b = 0; b < A1_BLOCKS; b++) c += g_part_cont[b];
        g_amp = 1.f + 0.5f * (c / (float)N_NODES);
    }
}

// ---------------------------------------------------------------------------
// Main per-row kernel
#define G1_STRIDE 193   // avoid 32-way bank conflicts in gates phase

struct __align__(16) SmemB {
    float sx[64];            // 256
    int   tg[32];            // 128
    float sea[96];           // 384
    float base_s[128];       // 512
    float base_p[128];       // 512
    float raw[32];           // 128
    float sc[32];            // 128
    float gpart[3][32];      // 384   (total 2432, 16B aligned below)
    float A[32 * 64];        // 8192  (float4 accessed)
    float Hs[32 * 128];      // 16384
    float Ps[32 * 128];      // 16384 (float4 accessed)
    float G1s[32 * G1_STRIDE];
};
#define SMEM_B_BYTES ((int)sizeof(SmemB))

__global__ void __launch_bounds__(256) kB(
    const float* __restrict__ x, const void* __restrict__ eidx, const float* __restrict__ ea,
    const float* __restrict__ Ws1, const float* __restrict__ bs1,
    const float* __restrict__ ln_g, const float* __restrict__ ln_b,
    const float* __restrict__ Ws2, const float* __restrict__ bs2,
    const float* __restrict__ Wp,  const float* __restrict__ bp,
    const float* __restrict__ Wg1, const float* __restrict__ bg1,
    const float* __restrict__ Wg2, const float* __restrict__ bg2,
    float* __restrict__ out, int write_idx) {

    extern __shared__ char smraw[];
    SmemB& sm = *reinterpret_cast<SmemB*>(smraw);
    int t = threadIdx.x;
    int r = blockIdx.x;

    // ---- phase 0: loads -------------------------------------------------
    if (t < 64) sm.sx[t] = x[r * 64 + t];
    if (t >= 64 && t < 96) {
        int j = t - 64;
        int e = r * DEG + j;
        int tgv;
        if (g_is64) tgv = (int)((const long long*)eidx)[E_EDGES + e];
        else        tgv = ((const int*)eidx)[E_EDGES + e];
        sm.tg[j] = tgv;
    }
    if (t >= 96 && t < 192) sm.sea[t - 96] = ea[r * 96 + (t - 96)];
    __syncthreads();

    for (int idx = t; idx < 32 * 64; idx += 256)
        sm.A[idx] = x[sm.tg[idx >> 6] * 64 + (idx & 63)];

    if (t < 128) {
        float a = bs1[t];
        for (int d = 0; d < 64; d++) a += sm.sx[d] * Ws1[d * 128 + t];
        sm.base_s[t] = a;
    } else {
        int c = t - 128;
        float a = bp[c];
        for (int d = 0; d < 64; d++) a += sm.sx[d] * Wp[d * 128 + c];
        sm.base_p[c] = a;
    }
    __syncthreads();

    // ---- phase 1: H = edge_input @ Ws1 ; P = relu(edge_input @ Wp) ------
    const float4* A4 = reinterpret_cast<const float4*>(sm.A);
    int c = t & 127, half = t >> 7, j0 = half * 16;
    {
        float acc[16];
        #pragma unroll
        for (int jj = 0; jj < 16; jj++) acc[jj] = sm.base_s[c];
        const float* W = Ws1 + 64 * 128 + c;
        #pragma unroll 4
        for (int d4 = 0; d4 < 16; d4++) {
            float w0 = W[(d4 * 4 + 0) * 128], w1 = W[(d4 * 4 + 1) * 128];
            float w2 = W[(d4 * 4 + 2) * 128], w3 = W[(d4 * 4 + 3) * 128];
            #pragma unroll
            for (int jj = 0; jj < 16; jj++) {
                float4 a = A4[(j0 + jj) * 16 + d4];
                acc[jj] += a.x * w0 + a.y * w1 + a.z * w2 + a.w * w3;
            }
        }
        float e0 = Ws1[128 * 128 + c], e1 = Ws1[129 * 128 + c], e2 = Ws1[130 * 128 + c];
        #pragma unroll
        for (int jj = 0; jj < 16; jj++) {
            const float* eaj = sm.sea + (j0 + jj) * 3;
            acc[jj] += eaj[0] * e0 + eaj[1] * e1 + eaj[2] * e2;
            sm.Hs[(j0 + jj) * 128 + c] = acc[jj];
        }
    }
    {
        float acc[16];
        #pragma unroll
        for (int jj = 0; jj < 16; jj++) acc[jj] = sm.base_p[c];
        const float* W = Wp + 64 * 128 + c;
        #pragma unroll 4
        for (int d4 = 0; d4 < 16; d4++) {
            float w0 = W[(d4 * 4 + 0) * 128], w1 = W[(d4 * 4 + 1) * 128];
            float w2 = W[(d4 * 4 + 2) * 128], w3 = W[(d4 * 4 + 3) * 128];
            #pragma unroll
            for (int jj = 0; jj < 16; jj++) {
                float4 a = A4[(j0 + jj) * 16 + d4];
                acc[jj] += a.x * w0 + a.y * w1 + a.z * w2 + a.w * w3;
            }
        }
        float e0 = Wp[128 * 128 + c], e1 = Wp[129 * 128 + c], e2 = Wp[130 * 128 + c];
        #pragma unroll
        for (int jj = 0; jj < 16; jj++) {
            const float* eaj = sm.sea + (j0 + jj) * 3;
            acc[jj] += eaj[0] * e0 + eaj[1] * e1 + eaj[2] * e2;
            sm.Ps[(j0 + jj) * 128 + c] = fmaxf(acc[jj], 0.f);
        }
    }
    __syncthreads();

    // ---- phase 2: LayerNorm + LeakyReLU + score_raw (warp per 4 edges) --
    {
        int w = t >> 5, l = t & 31;
        for (int q = 0; q < 4; q++) {
            int j = w * 4 + q;
            const float* hj = sm.Hs + j * 128;
            float v0 = hj[l], v1 = hj[l + 32], v2 = hj[l + 64], v3 = hj[l + 96];
            float s  = v0 + v1 + v2 + v3;
            float ss = v0 * v0 + v1 * v1 + v2 * v2 + v3 * v3;
            #pragma unroll
            for (int off = 16; off; off >>= 1) {
                s  += __shfl_xor_sync(0xffffffffu, s, off);
                ss += __shfl_xor_sync(0xffffffffu, ss, off);
            }
            float mu  = s * (1.f / 128.f);
            float var = fmaxf(ss * (1.f / 128.f) - mu * mu, 0.f);
            float inv = rsqrtf(var + EPS_LN);
            float contrib = 0.f;
            #pragma unroll
            for (int k4 = 0; k4 < 4; k4++) {
                int hh = l + 32 * k4;
                float hn = (hj[hh] - mu) * inv * ln_g[hh] + ln_b[hh];
                hn = hn >= 0.f ? hn : NEG * hn;
                contrib += hn * Ws2[hh];
            }
            #pragma unroll
            for (int off = 16; off; off >>= 1)
                contrib += __shfl_xor_sync(0xffffffffu, contrib, off);
            if (l == 0) sm.raw[j] = contrib + bs2[0];
        }
    }
    __syncthreads();

    // ---- phase 3: G1 = relu(P @ Wg1 + bg1) ------------------------------
    if (t < 192) {
        int rr = t >> 6, m = t & 63;
        float acc[32];
        float b = bg1[rr * 64 + m];
        #pragma unroll
        for (int j = 0; j < 32; j++) acc[j] = b;
        const float* Wg = Wg1 + rr * (128 * 64) + m;
        const float4* P4 = reinterpret_cast<const float4*>(sm.Ps);
        #pragma unroll 2
        for (int h4 = 0; h4 < 32; h4++) {
            float w0 = Wg[(h4 * 4 + 0) * 64], w1 = Wg[(h4 * 4 + 1) * 64];
            float w2 = Wg[(h4 * 4 + 2) * 64], w3 = Wg[(h4 * 4 + 3) * 64];
            #pragma unroll
            for (int j = 0; j < 32; j++) {
                float4 p = P4[j * 32 + h4];
                acc[j] += p.x * w0 + p.y * w1 + p.z * w2 + p.w * w3;
            }
        }
        #pragma unroll
        for (int j = 0; j < 32; j++) sm.G1s[j * G1_STRIDE + t] = fmaxf(acc[j], 0.f);
    }
    __syncthreads();

    // ---- phase 4: gates, combine ---------------------------------------
    if (t < 96) {
        int j = t & 31, rr = t >> 5;
        float s = bg2[rr];
        const float* g  = sm.G1s + j * G1_STRIDE + rr * 64;
        const float* w2 = Wg2 + rr * 64;
        #pragma unroll 8
        for (int m = 0; m < 64; m++) s += g[m] * w2[m];
        float gate = 1.f / (1.f + expf(-s));
        sm.gpart[rr][j] = gate * g_regime[rr];
    }
    __syncthreads();
    if (t < 32) {
        float gc = sm.gpart[0][t] + sm.gpart[1][t] + sm.gpart[2][t];
        sm.sc[t] = sm.raw[t] * gc * g_amp;
    }
    __syncthreads();

    // ---- phase 5: dedupe (last wins), softmax, sort, top-k fill ---------
    if (t < 32) {
        int j = t;
        int tgj = sm.tg[j];
        bool valid = true;
        for (int j2 = j + 1; j2 < 32; j2++)
            if (sm.tg[j2] == tgj) valid = false;
        float sval = sm.sc[j];
        float m = valid ? sval : -INFINITY;
        #pragma unroll
        for (int off = 16; off; off >>= 1)
            m = fmaxf(m, __shfl_xor_sync(0xffffffffu, m, off));
        float e = valid ? expf((sval - m) / TEMP) : 0.f;
        float sum = e;
        #pragma unroll
        for (int off = 16; off; off >>= 1)
            sum += __shfl_xor_sync(0xffffffffu, sum, off);
        float p = e / sum;

        unsigned vb = __ballot_sync(0xffffffffu, valid);
        int cnt = __popc(vb);
        int rank = 0;
        for (int j2 = 0; j2 < 32; j2++) {
            float p2 = __shfl_sync(0xffffffffu, p, j2);
            int  t2 = __shfl_sync(0xffffffffu, tgj, j2);
            bool v2 = (vb >> j2) & 1u;
            if (valid && v2 && j2 != j &&
                (p2 > p || (p2 == p && t2 < tgj))) rank++;
        }
        float* wout = out + (size_t)r * K_TOP;
        float* iout = out + (size_t)N_NODES * K_TOP + (size_t)r * K_TOP;
        if (valid) {
            wout[rank] = (p > THRESH) ? p : 0.f;
            if (write_idx) iout[rank] = (float)tgj;
        }
        if (j == 0 && cnt < 32) {
            int slot = cnt, v = 0;
            while (slot < 32) {
                bool member = false;
                for (int j2 = 0; j2 < 32; j2++)
                    if (((vb >> j2) & 1u) && sm.tg[j2] == v) member = true;
                if (!member) {
                    wout[slot] = 0.f;
                    if (write_idx) iout[slot] = (float)v;
                    slot++;
                }
                v++;
            }
        }
    }
}

// ---------------------------------------------------------------------------
extern "C" void kernel_launch(void* const* d_in, const int* in_sizes, int n_in,
                              void* d_out, int out_size) {
    const float* x    = (const float*)d_in[0];
    const void*  eidx = d_in[1];
    const float* ea   = (const float*)d_in[2];
    const float* Ws1  = (const float*)d_in[3];
    const float* bs1  = (const float*)d_in[4];
    const float* ln_g = (const float*)d_in[5];
    const float* ln_b = (const float*)d_in[6];
    const float* Ws2  = (const float*)d_in[7];
    const float* bs2  = (const float*)d_in[8];
    const float* Wp   = (const float*)d_in[9];
    const float* bp   = (const float*)d_in[10];
    const float* Wr1  = (const float*)d_in[11];
    const float* br1  = (const float*)d_in[12];
    const float* Wr2  = (const float*)d_in[13];
    const float* br2  = (const float*)d_in[14];
    const float* Wg1  = (const float*)d_in[15];
    const float* bg1  = (const float*)d_in[16];
    const float* Wg2  = (const float*)d_in[17];
    const float* bg2  = (const float*)d_in[18];
    const float* Wc1  = (const float*)d_in[19];
    const float* bc1  = (const float*)d_in[20];
    const float* Wc2  = (const float*)d_in[21];
    const float* bc2  = (const float*)d_in[22];
    float* out = (float*)d_out;

    int write_idx = (out_size >= 2 * N_NODES * K_TOP) ? 1 : 0;

    cudaFuncSetAttribute(kB, cudaFuncAttributeMaxDynamicSharedMemorySize, SMEM_B_BYTES);

    kDetect<<<1, 1>>>(eidx);
    kA1<<<A1_BLOCKS, 256>>>(x, Wc1, bc1, Wc2, bc2);
    kA2<<<1, 128>>>(Wr1, br1, Wr2, br2);
    kB<<<N_NODES, 256, SMEM_B_BYTES>>>(x, eidx, ea,
        Ws1, bs1, ln_g, ln_b, Ws2, bs2, Wp, bp,
        Wg1, bg1, Wg2, bg2, out, write_idx);
}

// round 4
// speedup vs baseline: 1.1387x; 1.1387x over previous
#include <cuda_runtime.h>
#include <math.h>

#define N_NODES 8192
#define F_DIM   64
#define H_DIM   128
#define R_DIM   3
#define DEG     32
#define K_TOP   32
#define E_EDGES (N_NODES*DEG)
#define TEMP    0.3f
#define NEG     0.2f
#define EPS_LN  1e-5f
#define THRESH  1e-6f

#define A1_BLOCKS 256   // 32 nodes per block

// deterministic scratch (no atomics)
__device__ float g_part_gs[A1_BLOCKS * F_DIM];
__device__ float g_part_cont[A1_BLOCKS];
__device__ float g_regime[R_DIM];
__device__ float g_amp;

// ---------------------------------------------------------------------------
// A1: per-block (32 nodes) partial column sums of x, and partial contagion sums
__global__ void kA1(const float* __restrict__ x,
                    const float* __restrict__ Wc1, const float* __restrict__ bc1,
                    const float* __restrict__ Wc2, const float* __restrict__ bc2) {
    __shared__ float xs[32][64];
    __shared__ float colsum[4][64];
    __shared__ float cwarp[8];
    int t = threadIdx.x, b = blockIdx.x;
    int base = b * 32;
    for (int idx = t; idx < 32 * 64; idx += 256)
        xs[idx >> 6][idx & 63] = x[base * 64 + idx];
    __syncthreads();
    // gs partials
    {
        int col = t & 63, g = t >> 6;
        float s = 0.f;
        #pragma unroll
        for (int rr = 0; rr < 8; rr++) s += xs[g * 8 + rr][col];
        colsum[g][col] = s;
    }
    // contagion: warp w -> local nodes w*4 .. w*4+3
    int w = t >> 5, l = t & 31;
    float csum = 0.f;
    for (int q = 0; q < 4; q++) {
        int node = w * 4 + q;
        float a0 = bc1[l], a1 = bc1[l + 32], a2 = bc1[l + 64], a3 = bc1[l + 96];
        for (int d = 0; d < 64; d++) {
            float xv = xs[node][d];
            const float* Wd = Wc1 + d * 128;
            a0 += xv * Wd[l];      a1 += xv * Wd[l + 32];
            a2 += xv * Wd[l + 64]; a3 += xv * Wd[l + 96];
        }
        float s = fmaxf(a0, 0.f) * Wc2[l]      + fmaxf(a1, 0.f) * Wc2[l + 32]
                + fmaxf(a2, 0.f) * Wc2[l + 64] + fmaxf(a3, 0.f) * Wc2[l + 96];
        #pragma unroll
        for (int off = 16; off; off >>= 1) s += __shfl_xor_sync(0xffffffffu, s, off);
        if (l == 0) csum += 1.f / (1.f + expf(-(s + bc2[0])));
    }
    if (l == 0) cwarp[w] = csum;
    __syncthreads();
    if (t < 64) g_part_gs[b * 64 + t] = colsum[0][t] + colsum[1][t] + colsum[2][t] + colsum[3][t];
    if (t == 0) {
        float s = 0.f;
        for (int i = 0; i < 8; i++) s += cwarp[i];
        g_part_cont[b] = s;
    }
}

// ---------------------------------------------------------------------------
// A2: finalize gs mean, regime probs, contagion amp (1 block, 128 threads)
__global__ void kA2(const float* __restrict__ Wr1, const float* __restrict__ br1,
                    const float* __restrict__ Wr2, const float* __restrict__ br2) {
    __shared__ float gs[64];
    __shared__ float hr[128];
    int t = threadIdx.x;
    if (t < 64) {
        float s = 0.f;
        for (int b = 0; b < A1_BLOCKS; b++) s += g_part_gs[b * 64 + t];
        gs[t] = s / (float)N_NODES;
    }
    __syncthreads();
    {
        float a = br1[t];
        for (int d = 0; d < 64; d++) a += gs[d] * Wr1[d * 128 + t];
        hr[t] = fmaxf(a, 0.f);
    }
    __syncthreads();
    if (t == 0) {
        float lg[3];
        for (int r = 0; r < 3; r++) {
            float a = br2[r];
            for (int h = 0; h < 128; h++) a += hr[h] * Wr2[h * 3 + r];
            lg[r] = a;
        }
        float m = fmaxf(lg[0], fmaxf(lg[1], lg[2]));
        float e0 = expf(lg[0] - m), e1 = expf(lg[1] - m), e2 = expf(lg[2] - m);
        float s = e0 + e1 + e2;
        g_regime[0] = e0 / s; g_regime[1] = e1 / s; g_regime[2] = e2 / s;
        float c = 0.f;
        for (int b = 0; b < A1_BLOCKS; b++) c += g_part_cont[b];
        g_amp = 1.f + 0.5f * (c / (float)N_NODES);
    }
}

// ---------------------------------------------------------------------------
// Main per-row kernel. Shared memory layout (floats):
//   [0:64)          sx
//   [64:96)         tg (int)
//   [96:192)        sea
//   [192:320)       base_s
//   [320:448)       base_p
//   [448:480)       raw
//   [480:512)       sc
//   [512:608)       gpart[3][32]
//   [608:2656)      A   (32x64)        -- dead after phase 1
//   [2656:6752)     Hs  (32x128)       -- dead after phase 2
//   [6752:10848)    Ps  (32x128)
//   G1s aliases [608:6752)  (3*32*64 = 6144 floats, rotation layout)
#define SM_FIXED 608
#define SM_A     608
#define SM_HS    2656
#define SM_PS    6752
#define SM_TOTAL 10848
#define SMEM_B_BYTES (SM_TOTAL * 4)

__global__ void __launch_bounds__(256, 4) kB(
    const float* __restrict__ x, const void* __restrict__ eidx, const float* __restrict__ ea,
    const float* __restrict__ Ws1, const float* __restrict__ bs1,
    const float* __restrict__ ln_g, const float* __restrict__ ln_b,
    const float* __restrict__ Ws2, const float* __restrict__ bs2,
    const float* __restrict__ Wp,  const float* __restrict__ bp,
    const float* __restrict__ Wg1, const float* __restrict__ bg1,
    const float* __restrict__ Wg2, const float* __restrict__ bg2,
    float* __restrict__ out, int write_idx) {

    extern __shared__ float smf[];
    float* sx     = smf;
    int*   tg     = (int*)(smf + 64);
    float* sea    = smf + 96;
    float* base_s = smf + 192;
    float* base_p = smf + 320;
    float* raw    = smf + 448;
    float* sc     = smf + 480;
    float* gpart  = smf + 512;          // [3][32]
    float* A      = smf + SM_A;
    float* Hs     = smf + SM_HS;
    float* Ps     = smf + SM_PS;
    float* G1s    = smf + SM_A;         // aliases A+Hs (phase 3+)

    int t = threadIdx.x;
    int r = blockIdx.x;

    // ---- phase 0: loads -------------------------------------------------
    if (t < 64) sx[t] = x[r * 64 + t];
    if (t >= 64 && t < 96) {
        int j = t - 64;
        int e = r * DEG + j;
        // detect int32 vs int64 edge_index: src=repeat(arange(N),32) so
        // ((ll*)p)[32] == 1 iff int64 layout.
        const long long* p64 = (const long long*)eidx;
        int tgv;
        if (p64[32] == 1LL) tgv = (int)p64[E_EDGES + e];
        else                tgv = ((const int*)eidx)[E_EDGES + e];
        tg[j] = tgv;
    }
    if (t >= 96 && t < 192) sea[t - 96] = ea[r * 96 + (t - 96)];
    __syncthreads();

    {
        const float4* x4 = (const float4*)x;
        float4* A4w = (float4*)A;
        for (int idx = t; idx < 32 * 16; idx += 256)
            A4w[idx] = x4[tg[idx >> 4] * 16 + (idx & 15)];
    }

    if (t < 128) {
        float a = bs1[t];
        for (int d = 0; d < 64; d++) a += sx[d] * Ws1[d * 128 + t];
        base_s[t] = a;
    } else {
        int c = t - 128;
        float a = bp[c];
        for (int d = 0; d < 64; d++) a += sx[d] * Wp[d * 128 + c];
        base_p[c] = a;
    }
    __syncthreads();

    // ---- phase 1: H = edge_input @ Ws1 ; P = relu(edge_input @ Wp) ------
    const float4* A4 = (const float4*)A;
    int c = t & 127, half0 = t >> 7, j0 = half0 * 16;
    {
        float acc[16];
        #pragma unroll
        for (int jj = 0; jj < 16; jj++) acc[jj] = base_s[c];
        const float* W = Ws1 + 64 * 128 + c;
        #pragma unroll 4
        for (int d4 = 0; d4 < 16; d4++) {
            float w0 = W[(d4 * 4 + 0) * 128], w1 = W[(d4 * 4 + 1) * 128];
            float w2 = W[(d4 * 4 + 2) * 128], w3 = W[(d4 * 4 + 3) * 128];
            #pragma unroll
            for (int jj = 0; jj < 16; jj++) {
                float4 a = A4[(j0 + jj) * 16 + d4];
                acc[jj] += a.x * w0 + a.y * w1 + a.z * w2 + a.w * w3;
            }
        }
        float e0 = Ws1[128 * 128 + c], e1 = Ws1[129 * 128 + c], e2 = Ws1[130 * 128 + c];
        #pragma unroll
        for (int jj = 0; jj < 16; jj++) {
            const float* eaj = sea + (j0 + jj) * 3;
            acc[jj] += eaj[0] * e0 + eaj[1] * e1 + eaj[2] * e2;
            Hs[(j0 + jj) * 128 + c] = acc[jj];
        }
    }
    {
        float acc[16];
        #pragma unroll
        for (int jj = 0; jj < 16; jj++) acc[jj] = base_p[c];
        const float* W = Wp + 64 * 128 + c;
        #pragma unroll 4
        for (int d4 = 0; d4 < 16; d4++) {
            float w0 = W[(d4 * 4 + 0) * 128], w1 = W[(d4 * 4 + 1) * 128];
            float w2 = W[(d4 * 4 + 2) * 128], w3 = W[(d4 * 4 + 3) * 128];
            #pragma unroll
            for (int jj = 0; jj < 16; jj++) {
                float4 a = A4[(j0 + jj) * 16 + d4];
                acc[jj] += a.x * w0 + a.y * w1 + a.z * w2 + a.w * w3;
            }
        }
        float e0 = Wp[128 * 128 + c], e1 = Wp[129 * 128 + c], e2 = Wp[130 * 128 + c];
        #pragma unroll
        for (int jj = 0; jj < 16; jj++) {
            const float* eaj = sea + (j0 + jj) * 3;
            acc[jj] += eaj[0] * e0 + eaj[1] * e1 + eaj[2] * e2;
            Ps[(j0 + jj) * 128 + c] = fmaxf(acc[jj], 0.f);
        }
    }
    __syncthreads();

    // ---- phase 2: LayerNorm + LeakyReLU + score_raw (warp per 4 edges) --
    {
        int w = t >> 5, l = t & 31;
        for (int q = 0; q < 4; q++) {
            int j = w * 4 + q;
            const float* hj = Hs + j * 128;
            float v0 = hj[l], v1 = hj[l + 32], v2 = hj[l + 64], v3 = hj[l + 96];
            float s  = v0 + v1 + v2 + v3;
            float ss = v0 * v0 + v1 * v1 + v2 * v2 + v3 * v3;
            #pragma unroll
            for (int off = 16; off; off >>= 1) {
                s  += __shfl_xor_sync(0xffffffffu, s, off);
                ss += __shfl_xor_sync(0xffffffffu, ss, off);
            }
            float mu  = s * (1.f / 128.f);
            float var = fmaxf(ss * (1.f / 128.f) - mu * mu, 0.f);
            float inv = rsqrtf(var + EPS_LN);
            float vv[4] = {v0, v1, v2, v3};
            float contrib = 0.f;
            #pragma unroll
            for (int k4 = 0; k4 < 4; k4++) {
                int hh = l + 32 * k4;
                float hn = (vv[k4] - mu) * inv * ln_g[hh] + ln_b[hh];
                hn = hn >= 0.f ? hn : NEG * hn;
                contrib += hn * Ws2[hh];
            }
            #pragma unroll
            for (int off = 16; off; off >>= 1)
                contrib += __shfl_xor_sync(0xffffffffu, contrib, off);
            if (l == 0) raw[j] = contrib + bs2[0];
        }
    }
    __syncthreads();

    // ---- phase 3: G1 = relu(P @ Wg1 + bg1), rotation layout -------------
    // G1 value (rr, j, m) stored at G1s[rr*2048 + j*64 + ((m+j)&63)]
    if (t < 192) {
        int rr = t >> 6, m = t & 63;
        const float* Wg = Wg1 + rr * (128 * 64) + m;
        float b = bg1[rr * 64 + m];
        const float4* P4 = (const float4*)Ps;
        #pragma unroll
        for (int half = 0; half < 2; half++) {
            float acc[16];
            #pragma unroll
            for (int jj = 0; jj < 16; jj++) acc[jj] = b;
            #pragma unroll 2
            for (int h4 = 0; h4 < 32; h4++) {
                float w0 = Wg[(h4 * 4 + 0) * 64], w1 = Wg[(h4 * 4 + 1) * 64];
                float w2 = Wg[(h4 * 4 + 2) * 64], w3 = Wg[(h4 * 4 + 3) * 64];
                #pragma unroll
                for (int jj = 0; jj < 16; jj++) {
                    float4 p = P4[(half * 16 + jj) * 32 + h4];
                    acc[jj] += p.x * w0 + p.y * w1 + p.z * w2 + p.w * w3;
                }
            }
            #pragma unroll
            for (int jj = 0; jj < 16; jj++) {
                int j = half * 16 + jj;
                G1s[rr * 2048 + j * 64 + ((m + j) & 63)] = fmaxf(acc[jj], 0.f);
            }
        }
    }
    __syncthreads();

    // ---- phase 4: gates, combine ---------------------------------------
    if (t < 96) {
        int j = t & 31, rr = t >> 5;
        float s = bg2[rr];
        const float* g  = G1s + rr * 2048 + j * 64;
        const float* w2 = Wg2 + rr * 64;
        #pragma unroll 8
        for (int m = 0; m < 64; m++) s += g[(m + j) & 63] * w2[m];
        float gate = 1.f / (1.f + expf(-s));
        gpart[rr * 32 + j] = gate * g_regime[rr];
    }
    __syncthreads();
    if (t < 32) {
        float gc = gpart[t] + gpart[32 + t] + gpart[64 + t];
        sc[t] = raw[t] * gc * g_amp;
    }
    __syncthreads();

    // ---- phase 5: dedupe (last wins), softmax, sort, top-k fill ---------
    if (t < 32) {
        int j = t;
        int tgj = tg[j];
        bool valid = true;
        for (int j2 = j + 1; j2 < 32; j2++)
            if (tg[j2] == tgj) valid = false;
        float sval = sc[j];
        float m = valid ? sval : -INFINITY;
        #pragma unroll
        for (int off = 16; off; off >>= 1)
            m = fmaxf(m, __shfl_xor_sync(0xffffffffu, m, off));
        float e = valid ? expf((sval - m) / TEMP) : 0.f;
        float sum = e;
        #pragma unroll
        for (int off = 16; off; off >>= 1)
            sum += __shfl_xor_sync(0xffffffffu, sum, off);
        float p = e / sum;

        unsigned vb = __ballot_sync(0xffffffffu, valid);
        int cnt = __popc(vb);
        int rank = 0;
        for (int j2 = 0; j2 < 32; j2++) {
            float p2 = __shfl_sync(0xffffffffu, p, j2);
            int  t2 = __shfl_sync(0xffffffffu, tgj, j2);
            bool v2 = (vb >> j2) & 1u;
            if (valid && v2 && j2 != j &&
                (p2 > p || (p2 == p && t2 < tgj))) rank++;
        }
        float* wout = out + (size_t)r * K_TOP;
        float* iout = out + (size_t)N_NODES * K_TOP + (size_t)r * K_TOP;
        if (valid) {
            wout[rank] = (p > THRESH) ? p : 0.f;
            if (write_idx) iout[rank] = (float)tgj;
        }
        if (j == 0 && cnt < 32) {
            int slot = cnt, v = 0;
            while (slot < 32) {
                bool member = false;
                for (int j2 = 0; j2 < 32; j2++)
                    if (((vb >> j2) & 1u) && tg[j2] == v) member = true;
                if (!member) {
                    wout[slot] = 0.f;
                    if (write_idx) iout[slot] = (float)v;
                    slot++;
                }
                v++;
            }
        }
    }
}

// ---------------------------------------------------------------------------
extern "C" void kernel_launch(void* const* d_in, const int* in_sizes, int n_in,
                              void* d_out, int out_size) {
    const float* x    = (const float*)d_in[0];
    const void*  eidx = d_in[1];
    const float* ea   = (const float*)d_in[2];
    const float* Ws1  = (const float*)d_in[3];
    const float* bs1  = (const float*)d_in[4];
    const float* ln_g = (const float*)d_in[5];
    const float* ln_b = (const float*)d_in[6];
    const float* Ws2  = (const float*)d_in[7];
    const float* bs2  = (const float*)d_in[8];
    const float* Wp   = (const float*)d_in[9];
    const float* bp   = (const float*)d_in[10];
    const float* Wr1  = (const float*)d_in[11];
    const float* br1  = (const float*)d_in[12];
    const float* Wr2  = (const float*)d_in[13];
    const float* br2  = (const float*)d_in[14];
    const float* Wg1  = (const float*)d_in[15];
    const float* bg1  = (const float*)d_in[16];
    const float* Wg2  = (const float*)d_in[17];
    const float* bg2  = (const float*)d_in[18];
    const float* Wc1  = (const float*)d_in[19];
    const float* bc1  = (const float*)d_in[20];
    const float* Wc2  = (const float*)d_in[21];
    const float* bc2  = (const float*)d_in[22];
    float* out = (float*)d_out;

    int write_idx = (out_size >= 2 * N_NODES * K_TOP) ? 1 : 0;

    cudaFuncSetAttribute(kB, cudaFuncAttributeMaxDynamicSharedMemorySize, SMEM_B_BYTES);

    kA1<<<A1_BLOCKS, 256>>>(x, Wc1, bc1, Wc2, bc2);
    kA2<<<1, 128>>>(Wr1, br1, Wr2, br2);
    kB<<<N_NODES, 256, SMEM_B_BYTES>>>(x, eidx, ea,
        Ws1, bs1, ln_g, ln_b, Ws2, bs2, Wp, bp,
        Wg1, bg1, Wg2, bg2, out, write_idx);
}